// round 7
// baseline (speedup 1.0000x reference)
#include <cuda_runtime.h>
#include <math_constants.h>

// Problem constants (match reference)
#define POOLK 7
#define NUM_ROIS 300
#define FH 50
#define FW 50
#define FC 512

#define NPOS   (FH * FW)                              // 2500
#define NBINS  (NUM_ROIS * POOLK * POOLK)             // 14700
#define TOTAL_V4 (NUM_ROIS * POOLK * POOLK * (FC/4))  // 1,881,600 float4

// Write kernel geometry: exact cover, no bounds checks
#define WR_BLOCKS 1470
#define WR_THREADS 256
#define WR_STRIDE (WR_BLOCKS * WR_THREADS)            // 376,320
#define WR_ITERS 5                                    // 376320*5 == TOTAL_V4

// Scratch (no cudaMalloc allowed)
__device__ float g_fmax[NPOS];
__device__ float g_bins[NBINS];

// ---------------------------------------------------------------------------
// Kernel A: fmax[h][w] = max_c feature_maps[h][w][c]
// One WARP per position; each lane issues 4 independent float4 loads
// (MLP=4), 15 fmax + 5 shuffles, lane 0 stores. No barriers, no smem.
// ---------------------------------------------------------------------------
__global__ void __launch_bounds__(256) channel_max_kernel(const float* __restrict__ fm) {
    const int gtid = blockIdx.x * 256 + threadIdx.x;
    const int pos  = gtid >> 5;                 // warp id = position
    const int lane = gtid & 31;
    if (pos >= NPOS) return;

    const float4* __restrict__ p =
        reinterpret_cast<const float4*>(fm + (size_t)pos * FC);

    // 4 independent 512B-coalesced loads per warp quarter
    float4 a = p[lane];
    float4 b = p[lane + 32];
    float4 c = p[lane + 64];
    float4 d = p[lane + 96];

    float m0 = fmaxf(fmaxf(a.x, a.y), fmaxf(a.z, a.w));
    float m1 = fmaxf(fmaxf(b.x, b.y), fmaxf(b.z, b.w));
    float m2 = fmaxf(fmaxf(c.x, c.y), fmaxf(c.z, c.w));
    float m3 = fmaxf(fmaxf(d.x, d.y), fmaxf(d.z, d.w));
    float m  = fmaxf(fmaxf(m0, m1), fmaxf(m2, m3));

    #pragma unroll
    for (int o = 16; o > 0; o >>= 1)
        m = fmaxf(m, __shfl_xor_sync(0xffffffffu, m, o));

    if (lane == 0) g_fmax[pos] = m;
}

// ---------------------------------------------------------------------------
// Kernel B: one thread per (roi, bin). Fully-unrolled 5x5 predicated window
// max (window span provably <= 5 since rh,rw <= 26) so all loads pipeline
// into one L2 round-trip.
// ---------------------------------------------------------------------------
__global__ void __launch_bounds__(256) bins_kernel(const float* __restrict__ rois) {
    const int idx = blockIdx.x * 256 + threadIdx.x;
    if (idx >= NBINS) return;

    const int roi = idx / (POOLK * POOLK);
    const int b   = idx - roi * (POOLK * POOLK);
    const int bi  = b / POOLK;
    const int bj  = b - bi * POOLK;

    const float* r = rois + (size_t)roi * 5;
    const int x1 = (int)(__ldg(r + 1) * 0.0625f);   // exact: /16, non-negative
    const int y1 = (int)(__ldg(r + 2) * 0.0625f);
    const int x2 = (int)(__ldg(r + 3) * 0.0625f);
    const int y2 = (int)(__ldg(r + 4) * 0.0625f);
    const int rh = y2 - y1 + 1;
    const int rw = x2 - x1 + 1;

    int hs = y1 + (bi * rh) / POOLK;
    int he = y1 + ((bi + 1) * rh + POOLK - 1) / POOLK;
    int ws = x1 + (bj * rw) / POOLK;
    int we = x1 + ((bj + 1) * rw + POOLK - 1) / POOLK;
    hs = min(max(hs, 0), FH);  he = min(max(he, 0), FH);
    ws = min(max(ws, 0), FW);  we = min(max(we, 0), FW);

    const int hh = he - hs;   // <= 5
    const int ww = we - ws;   // <= 5

    float m = -CUDART_INF_F;
    #pragma unroll
    for (int dr = 0; dr < 5; ++dr) {
        #pragma unroll
        for (int dc = 0; dc < 5; ++dc) {
            if (dr < hh && dc < ww)
                m = fmaxf(m, g_fmax[(hs + dr) * FW + (ws + dc)]);
        }
    }
    g_bins[idx] = m;
}

// ---------------------------------------------------------------------------
// Kernel C: streaming broadcast write. Exact cover: 1470x256 threads,
// 5 fully independent (load, STG.128) pairs per thread — no loop-carried
// dependency, no bounds check.
// ---------------------------------------------------------------------------
__global__ void __launch_bounds__(WR_THREADS) write_kernel(float* __restrict__ out) {
    const int tid = blockIdx.x * WR_THREADS + threadIdx.x;
    float4* __restrict__ o4 = reinterpret_cast<float4*>(out);

    int   v[WR_ITERS];
    float f[WR_ITERS];
    #pragma unroll
    for (int k = 0; k < WR_ITERS; ++k) {
        v[k] = tid + k * WR_STRIDE;
        f[k] = __ldg(&g_bins[v[k] >> 7]);      // 128 float4 per bin; broadcast/L1-hit
    }
    #pragma unroll
    for (int k = 0; k < WR_ITERS; ++k)
        o4[v[k]] = make_float4(f[k], f[k], f[k], f[k]);
}

// ---------------------------------------------------------------------------
extern "C" void kernel_launch(void* const* d_in, const int* in_sizes, int n_in,
                              void* d_out, int out_size) {
    const float* rois = (const float*)d_in[0];
    const float* fm   = (const float*)d_in[1];
    if (n_in >= 2 && in_sizes[0] != NUM_ROIS * 5 && in_sizes[1] == NUM_ROIS * 5) {
        rois = (const float*)d_in[1];
        fm   = (const float*)d_in[0];
    }
    float* out = (float*)d_out;

    channel_max_kernel<<<(NPOS * 32 + 255) / 256, 256>>>(fm);
    bins_kernel<<<(NBINS + 255) / 256, 256>>>(rois);
    write_kernel<<<WR_BLOCKS, WR_THREADS>>>(out);
}

// round 9
// speedup vs baseline: 1.4060x; 1.4060x over previous
#include <cuda_runtime.h>
#include <math_constants.h>

// Problem constants (match reference)
#define POOLK 7
#define NUM_ROIS 300
#define FH 50
#define FW 50
#define FC 512

#define NPOS   (FH * FW)                    // 2500
#define NBINS  (NUM_ROIS * POOLK * POOLK)   // 14700

// Scratch (no cudaMalloc allowed)
__device__ float g_fmax[NPOS];

// ---------------------------------------------------------------------------
// Kernel A: fmax[h][w] = max_c feature_maps[h][w][c]
// One WARP per position; each lane issues 4 independent float4 loads
// (MLP=4), 15 fmax + 5 shuffles, lane 0 stores. No barriers, no smem.
// ---------------------------------------------------------------------------
__global__ void __launch_bounds__(256) channel_max_kernel(const float* __restrict__ fm) {
    const int gtid = blockIdx.x * 256 + threadIdx.x;
    const int pos  = gtid >> 5;
    const int lane = gtid & 31;
    if (pos >= NPOS) return;

    const float4* __restrict__ p =
        reinterpret_cast<const float4*>(fm + (size_t)pos * FC);

    float4 a = p[lane];
    float4 b = p[lane + 32];
    float4 c = p[lane + 64];
    float4 d = p[lane + 96];

    float m0 = fmaxf(fmaxf(a.x, a.y), fmaxf(a.z, a.w));
    float m1 = fmaxf(fmaxf(b.x, b.y), fmaxf(b.z, b.w));
    float m2 = fmaxf(fmaxf(c.x, c.y), fmaxf(c.z, c.w));
    float m3 = fmaxf(fmaxf(d.x, d.y), fmaxf(d.z, d.w));
    float m  = fmaxf(fmaxf(m0, m1), fmaxf(m2, m3));

    #pragma unroll
    for (int o = 16; o > 0; o >>= 1)
        m = fmaxf(m, __shfl_xor_sync(0xffffffffu, m, o));

    if (lane == 0) g_fmax[pos] = m;
}

// ---------------------------------------------------------------------------
// Kernel B': fused bin-compute + broadcast write. ONE WARP PER (roi, bin).
//   - lane l (<25) loads one window element (window provably <= 5x5),
//     predicated; single LDG per lane -> one L2 round trip per warp
//   - 5-step shuffle max reduction
//   - each lane stores 4 coalesced float4 (warp covers the bin's 2 KB)
// 14700 warps -> ~99 warps/SM: latency fully hidden; cost pinned at the
// STG.128 issue / LTS floor (~2.5-3 us for 30 MB).
// ---------------------------------------------------------------------------
__global__ void __launch_bounds__(256) roi_fused_kernel(const float* __restrict__ rois,
                                                        float* __restrict__ out) {
    const int gtid = blockIdx.x * 256 + threadIdx.x;
    const int wid  = gtid >> 5;              // global warp = (roi, bin)
    const int lane = gtid & 31;
    if (wid >= NBINS) return;

    const int roi = wid / (POOLK * POOLK);
    const int b   = wid - roi * (POOLK * POOLK);
    const int bi  = b / POOLK;
    const int bj  = b - bi * POOLK;

    // ROI coords (uniform across warp -> broadcast loads)
    const float* r = rois + (size_t)roi * 5;
    const int x1 = (int)(__ldg(r + 1) * 0.0625f);   // exact /16, non-negative
    const int y1 = (int)(__ldg(r + 2) * 0.0625f);
    const int x2 = (int)(__ldg(r + 3) * 0.0625f);
    const int y2 = (int)(__ldg(r + 4) * 0.0625f);
    const int rh = y2 - y1 + 1;                     // <= 26
    const int rw = x2 - x1 + 1;                     // <= 26

    int hs = y1 + (bi * rh) / POOLK;
    int he = y1 + ((bi + 1) * rh + POOLK - 1) / POOLK;
    int ws = x1 + (bj * rw) / POOLK;
    int we = x1 + ((bj + 1) * rw + POOLK - 1) / POOLK;
    hs = min(max(hs, 0), FH);  he = min(max(he, 0), FH);
    ws = min(max(ws, 0), FW);  we = min(max(we, 0), FW);

    const int hh = he - hs;   // <= 5
    const int ww = we - ws;   // <= 5

    // Lane-parallel window load: lane l -> (dr, dc) = (l/5, l%5), l < 25
    float m = -CUDART_INF_F;
    if (lane < 25) {
        const int dr = lane / 5;
        const int dc = lane - dr * 5;
        if (dr < hh && dc < ww)
            m = g_fmax[(hs + dr) * FW + (ws + dc)];
    }
    #pragma unroll
    for (int o = 16; o > 0; o >>= 1)
        m = fmaxf(m, __shfl_xor_sync(0xffffffffu, m, o));

    // Broadcast write: this warp owns 128 consecutive float4 (2 KB)
    float4* __restrict__ o4 =
        reinterpret_cast<float4*>(out) + (size_t)wid * (FC / 4);
    const float4 f4 = make_float4(m, m, m, m);
    o4[lane]      = f4;
    o4[lane + 32] = f4;
    o4[lane + 64] = f4;
    o4[lane + 96] = f4;
}

// ---------------------------------------------------------------------------
extern "C" void kernel_launch(void* const* d_in, const int* in_sizes, int n_in,
                              void* d_out, int out_size) {
    const float* rois = (const float*)d_in[0];
    const float* fm   = (const float*)d_in[1];
    if (n_in >= 2 && in_sizes[0] != NUM_ROIS * 5 && in_sizes[1] == NUM_ROIS * 5) {
        rois = (const float*)d_in[1];
        fm   = (const float*)d_in[0];
    }
    float* out = (float*)d_out;

    channel_max_kernel<<<(NPOS * 32 + 255) / 256, 256>>>(fm);
    roi_fused_kernel<<<(NBINS * 32 + 255) / 256, 256>>>(rois, out);
}